// round 1
// baseline (speedup 1.0000x reference)
#include <cuda_runtime.h>
#include <cstdint>

// out[o,m,n] = sum_{kh,j} w0[o,kh,j] * ( A[m, n+kh-4, j] + Bterm )
//   A[m,h,j] = sum_i x[i,m,h] * w1[i,0,j]
//   B[m,h,j] = sum_i x[i,m,h] * w1[i,1,j]
//   Bterm: n>=1 -> B[m, n+kh-5, j];  n==0 -> B[m, 51+kh, j]   (all zero-padded in h)
//
// Padded smem rows: Ae[h+5] = A[h], Be[h+5] = B[h], rows 0..4 and 61..65 zero.
//   A index -> row n+kh+1 ; B index -> row (n==0 ? 56 : n) + kh.

#define RS      15          // padded row stride (gcd(15,32)=1 -> conflict-free)
#define AEROWS  66
#define NTHREADS 112

__device__ __forceinline__ uint64_t pack2(float s) {
    uint64_t r;
    unsigned u = __float_as_uint(s);
    asm("mov.b64 %0, {%1, %1};" : "=l"(r) : "r"(u));
    return r;
}
__device__ __forceinline__ void ffma2(uint64_t& d, uint64_t a, uint64_t b) {
    asm("fma.rn.f32x2 %0, %1, %2, %0;" : "+l"(d) : "l"(a), "l"(b));
}
__device__ __forceinline__ float2 unpack2(uint64_t v) {
    unsigned lo, hi;
    asm("mov.b64 {%0, %1}, %2;" : "=r"(lo), "=r"(hi) : "l"(v));
    return make_float2(__uint_as_float(lo), __uint_as_float(hi));
}

__global__ __launch_bounds__(NTHREADS)
void fused_shiftconv_kernel(const float* __restrict__ x,
                            const float* __restrict__ w0,
                            const float* __restrict__ w1,
                            float* __restrict__ out)
{
    __shared__ float xs[24 * 56];                 // x[:, m, :]
    __shared__ float w1s[24 * 28];
    __shared__ float Ae[AEROWS * RS];
    __shared__ float Be[AEROWS * RS];
    __shared__ __align__(16) float w0s[126 * 32]; // [k][o_local]

    const int tid = threadIdx.x;
    const int m   = blockIdx.x;       // 0..55
    const int og  = blockIdx.y;       // 0..2  (32 o each)
    const int nh  = blockIdx.z;       // 0..1  (28 n each)

    // ---- Phase 1: loads + pad-row zeroing ----
    for (int t = tid; t < 24 * 56; t += NTHREADS)
        xs[t] = x[(t / 56) * 3136 + m * 56 + (t % 56)];
    for (int t = tid; t < 24 * 28; t += NTHREADS)
        w1s[t] = w1[t];
    // transpose w0 slice: w0s[k*32 + ol] = w0[(og*32+ol)*126 + k]
    for (int t = tid; t < 126 * 32; t += NTHREADS) {
        int ol = t & 31, k = t >> 5;
        w0s[t] = w0[(og * 32 + ol) * 126 + k];
    }
    // zero pad rows 0..4 and 61..65 of both Ae and Be
    for (int t = tid; t < 2 * 10 * RS; t += NTHREADS) {
        int arr = t / (10 * RS);
        int rr  = (t / RS) % 10;
        int c   = t % RS;
        int row = (rr < 5) ? rr : (56 + rr);
        if (arr) Be[row * RS + c] = 0.0f; else Ae[row * RS + c] = 0.0f;
    }
    __syncthreads();

    // ---- Phase 2: A/B interior (56 x 14 each) ----
    for (int t = tid; t < 56 * 14; t += NTHREADS) {
        int h = t / 14, j = t % 14;
        float a = 0.0f, b = 0.0f;
        #pragma unroll
        for (int i = 0; i < 24; i++) {
            float xv = xs[i * 56 + h];
            a = fmaf(xv, w1s[i * 28 + j],      a);
            b = fmaf(xv, w1s[i * 28 + 14 + j], b);
        }
        Ae[(h + 5) * RS + j] = a;
        Be[(h + 5) * RS + j] = b;
    }
    __syncthreads();

    // ---- Phase 3: main contraction ----
    const int nl = tid % 28;
    const int ow = tid / 28;                  // 0..3, 8 o's each
    const int n  = nh * 28 + nl;              // 0..55
    const int bBase = (n == 0) ? 56 : n;

    const float* aRow  = &Ae[(n + 1) * RS];
    const float* bRow  = &Be[bBase * RS];
    const float* wBase = &w0s[ow * 8];

    uint64_t acc0 = 0, acc1 = 0, acc2 = 0, acc3 = 0;

    #pragma unroll
    for (int kh = 0; kh < 9; kh++) {
        #pragma unroll
        for (int j = 0; j < 14; j++) {
            float s = aRow[kh * RS + j] + bRow[kh * RS + j];
            uint64_t s2 = pack2(s);
            const int k = kh * 14 + j;
            const ulonglong2* wp =
                reinterpret_cast<const ulonglong2*>(wBase + k * 32);
            ulonglong2 wv0 = wp[0];   // o_local+0..3
            ulonglong2 wv1 = wp[1];   // o_local+4..7
            ffma2(acc0, wv0.x, s2);
            ffma2(acc1, wv0.y, s2);
            ffma2(acc2, wv1.x, s2);
            ffma2(acc3, wv1.y, s2);
        }
    }

    // ---- store: out[o*3136 + m*56 + n] ----
    const int obase = og * 32 + ow * 8;
    float* op = out + m * 56 + n;
    float2 r;
    r = unpack2(acc0); op[(obase + 0) * 3136] = r.x; op[(obase + 1) * 3136] = r.y;
    r = unpack2(acc1); op[(obase + 2) * 3136] = r.x; op[(obase + 3) * 3136] = r.y;
    r = unpack2(acc2); op[(obase + 4) * 3136] = r.x; op[(obase + 5) * 3136] = r.y;
    r = unpack2(acc3); op[(obase + 6) * 3136] = r.x; op[(obase + 7) * 3136] = r.y;
}

extern "C" void kernel_launch(void* const* d_in, const int* in_sizes, int n_in,
                              void* d_out, int out_size)
{
    const float* x = (const float*)d_in[0];
    const float* w0;
    const float* w1;
    // defensive: identify weights by size (w0 = 96*9*14 = 12096, w1 = 24*2*14 = 672)
    if (in_sizes[1] == 12096) { w0 = (const float*)d_in[1]; w1 = (const float*)d_in[2]; }
    else                      { w0 = (const float*)d_in[2]; w1 = (const float*)d_in[1]; }
    float* out = (float*)d_out;

    dim3 grid(56, 3, 2);
    fused_shiftconv_kernel<<<grid, NTHREADS>>>(x, w0, w1, out);
}

// round 2
// speedup vs baseline: 1.0114x; 1.0114x over previous
#include <cuda_runtime.h>
#include <cstdint>

// out[o,m,n] = sum_{kh,j} w0[o,kh,j] * S[m, n+kh, j]       (n >= 1)
// out[o,m,0] = sum_{kh,j} w0[o,kh,j] * S0[m, kh, j]
//   S[m,r,j]  = A[m,r-4,j] + B[m,r-5,j]   (A,B zero-padded in h outside [0,55])
//   S0[m,kh,j]= (kh>=4 ? A[kh-4] : 0) + (kh<=4 ? B[51+kh] : 0)
//   A[m,h,j] = sum_i x[i,m,h]*w1[i,0,j],  B[m,h,j] = sum_i x[i,m,h]*w1[i,1,j]
//
// Scratch layout (transposed for coalesced n-reads):
//   Sg[((m*14 + j)*80) + r] : r in [0,63] = S rows, r in [64,72] = S0 rows.

__device__ float Sg[56 * 14 * 80];   // 250,880 B device scratch (no allocs)

__device__ __forceinline__ uint64_t pack2(float s) {
    uint64_t r;
    unsigned u = __float_as_uint(s);
    asm("mov.b64 %0, {%1, %1};" : "=l"(r) : "r"(u));
    return r;
}
__device__ __forceinline__ void ffma2(uint64_t& d, uint64_t a, uint64_t b) {
    asm("fma.rn.f32x2 %0, %1, %2, %0;" : "+l"(d) : "l"(a), "l"(b));
}
__device__ __forceinline__ float2 unpack2(uint64_t v) {
    unsigned lo, hi;
    asm("mov.b64 {%0, %1}, %2;" : "=r"(lo), "=r"(hi) : "l"(v));
    return make_float2(__uint_as_float(lo), __uint_as_float(hi));
}

// ───────────────────────── Kernel 1: build S ─────────────────────────
__global__ __launch_bounds__(256)
void build_S_kernel(const float* __restrict__ x, const float* __restrict__ w1)
{
    __shared__ float xs[24 * 56];
    __shared__ float w1s[24 * 28];
    const int m = blockIdx.x, tid = threadIdx.x;

    for (int t = tid; t < 24 * 56; t += 256)
        xs[t] = x[(t / 56) * 3136 + m * 56 + (t % 56)];
    for (int t = tid; t < 24 * 28; t += 256)
        w1s[t] = w1[t];
    __syncthreads();

    for (int it = tid; it < 14 * 73; it += 256) {
        const int j = it / 73;
        const int r = it % 73;
        float a = 0.0f, b = 0.0f;
        if (r < 64) {
            const int h = r - 4;                 // S row: A[h] + B[h-1]
            if (h >= 0 && h <= 55) {
                #pragma unroll
                for (int i = 0; i < 24; i++)
                    a = fmaf(xs[i * 56 + h], w1s[i * 28 + j], a);
            }
            if (h >= 1 && h <= 56) {
                #pragma unroll
                for (int i = 0; i < 24; i++)
                    b = fmaf(xs[i * 56 + h - 1], w1s[i * 28 + 14 + j], b);
            }
        } else {
            const int kh = r - 64;               // S0 row (n==0 wrap)
            if (kh >= 4) {
                const int ha = kh - 4;
                #pragma unroll
                for (int i = 0; i < 24; i++)
                    a = fmaf(xs[i * 56 + ha], w1s[i * 28 + j], a);
            }
            if (kh <= 4) {
                const int hb = 51 + kh;
                #pragma unroll
                for (int i = 0; i < 24; i++)
                    b = fmaf(xs[i * 56 + hb], w1s[i * 28 + 14 + j], b);
            }
        }
        Sg[(m * 14 + j) * 80 + r] = a + b;
    }
}

// ───────────────────────── Kernel 2: contraction ─────────────────────────
// grid (56 m, 6 og of 16 o, 2 nh of 28 n), block 112 = 28 n × 4 ow (4 o each)
__global__ __launch_bounds__(112)
void contract_kernel(const float* __restrict__ w0, float* __restrict__ out)
{
    __shared__ __align__(16) float w0s[126 * 16];   // [k][o_local]

    const int m  = blockIdx.x;
    const int og = blockIdx.y;
    const int nh = blockIdx.z;
    const int tid = threadIdx.x;

    for (int t = tid; t < 126 * 16; t += 112) {
        const int ol = t & 15, k = t >> 4;
        w0s[t] = w0[(og * 16 + ol) * 126 + k];
    }
    __syncthreads();

    const int nl = tid % 28;
    const int ow = tid / 28;                 // 0..3
    const int n  = nh * 28 + nl;
    const int rbase = (n == 0) ? 64 : n;     // n==0 -> S0 rows

    const float* __restrict__ sp = Sg + (m * 14) * 80 + rbase;

    uint64_t acc0 = 0, acc1 = 0;
    #pragma unroll
    for (int kh = 0; kh < 9; kh++) {
        #pragma unroll
        for (int j = 0; j < 14; j++) {
            const uint64_t s2 = pack2(sp[j * 80 + kh]);
            const ulonglong2 wv = *reinterpret_cast<const ulonglong2*>(
                &w0s[(kh * 14 + j) * 16 + ow * 4]);
            ffma2(acc0, wv.x, s2);
            ffma2(acc1, wv.y, s2);
        }
    }

    const int ob = og * 16 + ow * 4;
    float* op = out + m * 56 + n;
    float2 r;
    r = unpack2(acc0); op[(ob + 0) * 3136] = r.x; op[(ob + 1) * 3136] = r.y;
    r = unpack2(acc1); op[(ob + 2) * 3136] = r.x; op[(ob + 3) * 3136] = r.y;
}

extern "C" void kernel_launch(void* const* d_in, const int* in_sizes, int n_in,
                              void* d_out, int out_size)
{
    const float* x = (const float*)d_in[0];
    const float* w0;
    const float* w1;
    if (in_sizes[1] == 12096) { w0 = (const float*)d_in[1]; w1 = (const float*)d_in[2]; }
    else                      { w0 = (const float*)d_in[2]; w1 = (const float*)d_in[1]; }
    float* out = (float*)d_out;

    build_S_kernel<<<56, 256>>>(x, w1);
    contract_kernel<<<dim3(56, 6, 2), 112>>>(w0, out);
}